// round 2
// baseline (speedup 1.0000x reference)
#include <cuda_runtime.h>

#define BB 2
#define SS 512
#define DD 256
#define BS (BB*SS)
#define TI 8

// Scratch (allocation-free rule: __device__ globals). 1 MB each.
__device__ float g_E[BS*DD];
__device__ float g_R[BS*DD];

__device__ __forceinline__ float frcp_approx(float x){
    float r; asm("rcp.approx.f32 %0, %1;" : "=f"(r) : "f"(x)); return r;
}

// K1: P = Q @ Wm^T, then E = exp(2P), R = exp(-2P).
// Block = 256 threads handles TI=8 rows x all 256 e-cols. Thread e owns column e.
__global__ void __launch_bounds__(256) k1_proj(const float* __restrict__ Q,
                                               const float* __restrict__ W){
    __shared__ float sQT[DD][TI];     // [k][m], 8 KB
    __shared__ float sW[256][33];     // padded stage of W[:, k0:k0+32], ~34 KB
    const int tid = threadIdx.x;
    const int r0  = blockIdx.x * TI;  // global row base over B*S

    #pragma unroll
    for (int m = 0; m < TI; m++) sQT[tid][m] = Q[(r0 + m) * DD + tid];

    float acc[TI];
    #pragma unroll
    for (int m = 0; m < TI; m++) acc[m] = 0.f;

    for (int k0 = 0; k0 < DD; k0 += 32) {
        __syncthreads();
        // Stage W[n][k0+c] for n=0..255, c=0..31 (coalesced float4 loads)
        #pragma unroll
        for (int i = 0; i < 8; i++) {
            int j4 = i * 256 + tid;
            int n  = j4 >> 3;
            int c4 = (j4 & 7) * 4;
            float4 w4 = *(const float4*)(W + n * DD + k0 + c4);
            sW[n][c4 + 0] = w4.x; sW[n][c4 + 1] = w4.y;
            sW[n][c4 + 2] = w4.z; sW[n][c4 + 3] = w4.w;
        }
        __syncthreads();
        #pragma unroll
        for (int c = 0; c < 32; c++) {
            float w = sW[tid][c];                       // conflict-free (stride 33)
            float4 q0 = *(const float4*)&sQT[k0 + c][0]; // broadcast
            float4 q1 = *(const float4*)&sQT[k0 + c][4];
            acc[0] = fmaf(w, q0.x, acc[0]); acc[1] = fmaf(w, q0.y, acc[1]);
            acc[2] = fmaf(w, q0.z, acc[2]); acc[3] = fmaf(w, q0.w, acc[3]);
            acc[4] = fmaf(w, q1.x, acc[4]); acc[5] = fmaf(w, q1.y, acc[5]);
            acc[6] = fmaf(w, q1.z, acc[6]); acc[7] = fmaf(w, q1.w, acc[7]);
        }
    }

    const float C2 = 2.885390081777927f; // 2*log2(e)
    #pragma unroll
    for (int m = 0; m < TI; m++) {
        float p = acc[m];
        g_E[(r0 + m) * DD + tid] = exp2f( C2 * p);
        g_R[(r0 + m) * DD + tid] = exp2f(-C2 * p);
    }
}

// K2: fused scores (tanh via E*R + rcp) -> softmax -> atten out -> context out.
// Block = 8 warps handles TI=8 i-rows against all 512 j.
__global__ void __launch_bounds__(256) k2_attn(const float* __restrict__ V,
                                               const float* __restrict__ vm,
                                               float* __restrict__ out_ctx,
                                               float* __restrict__ out_att){
    __shared__ float s_sc[SS][TI];    // 16 KB, s_sc[j][ti]
    const int tid  = threadIdx.x;
    const int lane = tid & 31;
    const int w    = tid >> 5;
    const int r0   = blockIdx.x * TI;
    const int b    = r0 / SS;
    const int jbase = b * SS;

    // vm in registers (e = 4*lane + c  and  128 + 4*lane + c), plus SV = sum(vm)
    const float4* vm4 = (const float4*)vm;
    float4 va = vm4[lane];
    float4 vb = vm4[32 + lane];
    float sv = va.x + va.y + va.z + va.w + vb.x + vb.y + vb.z + vb.w;
    #pragma unroll
    for (int off = 16; off; off >>= 1) sv += __shfl_xor_sync(0xffffffffu, sv, off);
    float4 v2a = make_float4(2.f*va.x, 2.f*va.y, 2.f*va.z, 2.f*va.w);
    float4 v2b = make_float4(2.f*vb.x, 2.f*vb.y, 2.f*vb.z, 2.f*vb.w);

    // R for the 8 i-rows, register-resident (same e-layout as E loads)
    float4 ra[TI], rb[TI];
    #pragma unroll
    for (int ti = 0; ti < TI; ti++) {
        const float4* Rr = (const float4*)(g_R + (r0 + ti) * DD);
        ra[ti] = Rr[lane];
        rb[ti] = Rr[32 + lane];
    }

    // Score phase: warp-strided over j; each warp computes 8 scores per j.
    const float4* E4 = (const float4*)(g_E + (long)jbase * DD);
    for (int j = w; j < SS; j += 8) {
        float4 ea = E4[j * 64 + lane];
        float4 eb = E4[j * 64 + 32 + lane];
        #pragma unroll
        for (int ti = 0; ti < TI; ti++) {
            float a;
            a = v2a.x *       frcp_approx(fmaf(ea.x, ra[ti].x, 1.f));
            a = fmaf(v2a.y,   frcp_approx(fmaf(ea.y, ra[ti].y, 1.f)), a);
            a = fmaf(v2a.z,   frcp_approx(fmaf(ea.z, ra[ti].z, 1.f)), a);
            a = fmaf(v2a.w,   frcp_approx(fmaf(ea.w, ra[ti].w, 1.f)), a);
            a = fmaf(v2b.x,   frcp_approx(fmaf(eb.x, rb[ti].x, 1.f)), a);
            a = fmaf(v2b.y,   frcp_approx(fmaf(eb.y, rb[ti].y, 1.f)), a);
            a = fmaf(v2b.z,   frcp_approx(fmaf(eb.z, rb[ti].z, 1.f)), a);
            a = fmaf(v2b.w,   frcp_approx(fmaf(eb.w, rb[ti].w, 1.f)), a);
            #pragma unroll
            for (int off = 16; off; off >>= 1)
                a += __shfl_xor_sync(0xffffffffu, a, off);
            if (lane == ti) s_sc[j][ti] = sv - a;   // score = SV - sum(2vm*rcp)
        }
    }
    __syncthreads();

    // Softmax over j: warp w owns row r0+w. Writes normalized atten to smem + gmem.
    {
        float mx = -1e30f;
        for (int j = lane; j < SS; j += 32) mx = fmaxf(mx, s_sc[j][w]);
        #pragma unroll
        for (int off = 16; off; off >>= 1)
            mx = fmaxf(mx, __shfl_xor_sync(0xffffffffu, mx, off));
        float sum = 0.f;
        for (int j = lane; j < SS; j += 32) {
            float e = __expf(s_sc[j][w] - mx);
            s_sc[j][w] = e;
            sum += e;
        }
        #pragma unroll
        for (int off = 16; off; off >>= 1)
            sum += __shfl_xor_sync(0xffffffffu, sum, off);
        float inv = 1.f / sum;
        const int r = r0 + w;
        for (int j = lane; j < SS; j += 32) {
            float a = s_sc[j][w] * inv;
            s_sc[j][w] = a;
            out_att[(long)r * SS + j] = a;
        }
    }
    __syncthreads();

    // AV: thread owns column d = tid; context[r0+ti][d] = sum_j atten*V
    float cacc[TI];
    #pragma unroll
    for (int ti = 0; ti < TI; ti++) cacc[ti] = 0.f;
    const float* Vb = V + (long)jbase * DD + tid;
    #pragma unroll 4
    for (int j = 0; j < SS; j++) {
        float vv = __ldg(Vb + (long)j * DD);            // coalesced across tid
        float4 a0 = *(const float4*)&s_sc[j][0];        // broadcast
        float4 a1 = *(const float4*)&s_sc[j][4];
        cacc[0] = fmaf(a0.x, vv, cacc[0]); cacc[1] = fmaf(a0.y, vv, cacc[1]);
        cacc[2] = fmaf(a0.z, vv, cacc[2]); cacc[3] = fmaf(a0.w, vv, cacc[3]);
        cacc[4] = fmaf(a1.x, vv, cacc[4]); cacc[5] = fmaf(a1.y, vv, cacc[5]);
        cacc[6] = fmaf(a1.z, vv, cacc[6]); cacc[7] = fmaf(a1.w, vv, cacc[7]);
    }
    #pragma unroll
    for (int ti = 0; ti < TI; ti++)
        out_ctx[(long)(r0 + ti) * DD + tid] = cacc[ti];
}

extern "C" void kernel_launch(void* const* d_in, const int* in_sizes, int n_in,
                              void* d_out, int out_size) {
    (void)in_sizes; (void)n_in; (void)out_size;
    const float* Q  = (const float*)d_in[0];
    // d_in[1] = key: unused by the reference computation
    const float* V  = (const float*)d_in[2];
    const float* Wm = (const float*)d_in[3];
    const float* vm = (const float*)d_in[4];
    float* out      = (float*)d_out;
    float* out_ctx  = out;              // context [B,S,D]
    float* out_att  = out + BS * DD;    // atten   [B,S,S]

    k1_proj<<<BS / TI, 256>>>(Q, Wm);
    k2_attn<<<BS / TI, 256>>>(V, vm, out_ctx, out_att);
}

// round 3
// speedup vs baseline: 1.5497x; 1.5497x over previous
#include <cuda_runtime.h>

#define BB 2
#define SS 512
#define DD 256
#define BS (BB*SS)
#define TI 8

// Scratch (allocation-free rule: __device__ globals).
__device__ float g_ET[BB*DD*SS];  // E transposed: [b][e][j] = exp(2*P[b][j][e])
__device__ float g_R [BS*DD];     // R row-major:  [r][e]    = exp(-2*P[r][e])

__device__ __forceinline__ float frcp_approx(float x){
    float r; asm("rcp.approx.f32 %0, %1;" : "=f"(r) : "f"(x)); return r;
}

// K1: P = Q @ Wm^T; then E_T = exp(2P) (transposed store), R = exp(-2P).
// Block = 256 threads handles TI=8 rows x all 256 e-cols. Thread e owns column e.
__global__ void __launch_bounds__(256) k1_proj(const float* __restrict__ Q,
                                               const float* __restrict__ W){
    __shared__ float sQT[DD][TI];     // [k][m]
    __shared__ float sW[256][33];     // padded stage of W[:, k0:k0+32]
    const int tid = threadIdx.x;
    const int r0  = blockIdx.x * TI;  // global row base over B*S

    #pragma unroll
    for (int m = 0; m < TI; m++) sQT[tid][m] = Q[(r0 + m) * DD + tid];

    float acc[TI];
    #pragma unroll
    for (int m = 0; m < TI; m++) acc[m] = 0.f;

    for (int k0 = 0; k0 < DD; k0 += 32) {
        __syncthreads();
        #pragma unroll
        for (int i = 0; i < 8; i++) {
            int j4 = i * 256 + tid;
            int n  = j4 >> 3;
            int c4 = (j4 & 7) * 4;
            float4 w4 = *(const float4*)(W + n * DD + k0 + c4);
            sW[n][c4 + 0] = w4.x; sW[n][c4 + 1] = w4.y;
            sW[n][c4 + 2] = w4.z; sW[n][c4 + 3] = w4.w;
        }
        __syncthreads();
        #pragma unroll
        for (int c = 0; c < 32; c++) {
            float w = sW[tid][c];
            float4 q0 = *(const float4*)&sQT[k0 + c][0];
            float4 q1 = *(const float4*)&sQT[k0 + c][4];
            acc[0] = fmaf(w, q0.x, acc[0]); acc[1] = fmaf(w, q0.y, acc[1]);
            acc[2] = fmaf(w, q0.z, acc[2]); acc[3] = fmaf(w, q0.w, acc[3]);
            acc[4] = fmaf(w, q1.x, acc[4]); acc[5] = fmaf(w, q1.y, acc[5]);
            acc[6] = fmaf(w, q1.z, acc[6]); acc[7] = fmaf(w, q1.w, acc[7]);
        }
    }

    const float C2 = 2.885390081777927f; // 2*log2(e)
    const int b  = r0 / SS;
    const int jr = r0 % SS;              // row-within-batch (TI divides SS)
    #pragma unroll
    for (int m = 0; m < TI; m++) {
        float p = acc[m];
        g_ET[(size_t)b * DD * SS + (size_t)tid * SS + (jr + m)] = exp2f( C2 * p);
        g_R [(size_t)(r0 + m) * DD + tid]                       = exp2f(-C2 * p);
    }
}

// K2: scores via thread-local e-reduction (no shuffles), softmax, AV.
// Block = 128 threads (4 warps), i-tile = 4, all 512 j. Warp w owns j-chunk of 128.
__global__ void __launch_bounds__(128) k2_attn(const float* __restrict__ V,
                                               const float* __restrict__ vm,
                                               float* __restrict__ out_ctx,
                                               float* __restrict__ out_att){
    __shared__ float sR[4][260];      // R rows for the 4 i's (padded)
    __shared__ float sm2[256];        // -2*vm[e]
    __shared__ float s_sc[4][516];    // scores [i][j] (pad keeps 16B align: 516%4==0)
    __shared__ float s_red[4];

    const int tid  = threadIdx.x;
    const int lane = tid & 31;
    const int w    = tid >> 5;
    const int r0   = blockIdx.x * 4;
    const int b    = r0 >> 9;         // r0 / SS
    const int jb   = b << 9;

    // Stage R rows, -2vm, and block-reduce sum(vm).
    float svp = 0.f;
    #pragma unroll
    for (int e = tid; e < DD; e += 128) {
        float vme = vm[e];
        sm2[e] = -2.f * vme;
        svp += vme;
        #pragma unroll
        for (int i = 0; i < 4; i++) sR[i][e] = g_R[(size_t)(r0 + i) * DD + e];
    }
    #pragma unroll
    for (int off = 16; off; off >>= 1) svp += __shfl_xor_sync(0xffffffffu, svp, off);
    if (lane == 0) s_red[w] = svp;
    __syncthreads();
    const float sv = s_red[0] + s_red[1] + s_red[2] + s_red[3];

    // ---- Score phase: acc[i][jc] = -2*sum_e vm[e]*rcp(E[j]*R[i]+1) ----
    float acc[4][4];
    #pragma unroll
    for (int i = 0; i < 4; i++)
        #pragma unroll
        for (int c = 0; c < 4; c++) acc[i][c] = 0.f;

    const float4* ET4 = (const float4*)(g_ET + (size_t)b * DD * SS);
    const int jq = w * 32 + lane;     // float4 column index in a 512-wide row

    #pragma unroll 2
    for (int e = 0; e < DD; e += 4) {
        float4 ev0 = ET4[(e + 0) * (SS/4) + jq];
        float4 ev1 = ET4[(e + 1) * (SS/4) + jq];
        float4 ev2 = ET4[(e + 2) * (SS/4) + jq];
        float4 ev3 = ET4[(e + 3) * (SS/4) + jq];
        float4 m2  = *(const float4*)&sm2[e];
        #pragma unroll
        for (int i = 0; i < 4; i++) {
            float4 rv = *(const float4*)&sR[i][e];
            acc[i][0] = fmaf(m2.x, frcp_approx(fmaf(ev0.x, rv.x, 1.f)), acc[i][0]);
            acc[i][1] = fmaf(m2.x, frcp_approx(fmaf(ev0.y, rv.x, 1.f)), acc[i][1]);
            acc[i][2] = fmaf(m2.x, frcp_approx(fmaf(ev0.z, rv.x, 1.f)), acc[i][2]);
            acc[i][3] = fmaf(m2.x, frcp_approx(fmaf(ev0.w, rv.x, 1.f)), acc[i][3]);

            acc[i][0] = fmaf(m2.y, frcp_approx(fmaf(ev1.x, rv.y, 1.f)), acc[i][0]);
            acc[i][1] = fmaf(m2.y, frcp_approx(fmaf(ev1.y, rv.y, 1.f)), acc[i][1]);
            acc[i][2] = fmaf(m2.y, frcp_approx(fmaf(ev1.z, rv.y, 1.f)), acc[i][2]);
            acc[i][3] = fmaf(m2.y, frcp_approx(fmaf(ev1.w, rv.y, 1.f)), acc[i][3]);

            acc[i][0] = fmaf(m2.z, frcp_approx(fmaf(ev2.x, rv.z, 1.f)), acc[i][0]);
            acc[i][1] = fmaf(m2.z, frcp_approx(fmaf(ev2.y, rv.z, 1.f)), acc[i][1]);
            acc[i][2] = fmaf(m2.z, frcp_approx(fmaf(ev2.z, rv.z, 1.f)), acc[i][2]);
            acc[i][3] = fmaf(m2.z, frcp_approx(fmaf(ev2.w, rv.z, 1.f)), acc[i][3]);

            acc[i][0] = fmaf(m2.w, frcp_approx(fmaf(ev3.x, rv.w, 1.f)), acc[i][0]);
            acc[i][1] = fmaf(m2.w, frcp_approx(fmaf(ev3.y, rv.w, 1.f)), acc[i][1]);
            acc[i][2] = fmaf(m2.w, frcp_approx(fmaf(ev3.z, rv.w, 1.f)), acc[i][2]);
            acc[i][3] = fmaf(m2.w, frcp_approx(fmaf(ev3.w, rv.w, 1.f)), acc[i][3]);
        }
    }

    // Write scores (STS.128, conflict-free: lanes consecutive 16B)
    const int j0 = w * 128 + lane * 4;
    #pragma unroll
    for (int i = 0; i < 4; i++) {
        float4 s4 = make_float4(acc[i][0] + sv, acc[i][1] + sv,
                                acc[i][2] + sv, acc[i][3] + sv);
        *(float4*)&s_sc[i][j0] = s4;
    }
    __syncthreads();

    // ---- Softmax: warp w owns row r0+w (contiguous smem reads) ----
    {
        float mx = -1e30f;
        for (int j = lane; j < SS; j += 32) mx = fmaxf(mx, s_sc[w][j]);
        #pragma unroll
        for (int off = 16; off; off >>= 1)
            mx = fmaxf(mx, __shfl_xor_sync(0xffffffffu, mx, off));
        float sum = 0.f;
        for (int j = lane; j < SS; j += 32) {
            float e = __expf(s_sc[w][j] - mx);
            s_sc[w][j] = e;
            sum += e;
        }
        #pragma unroll
        for (int off = 16; off; off >>= 1)
            sum += __shfl_xor_sync(0xffffffffu, sum, off);
        float inv = 1.f / sum;
        const size_t r = (size_t)(r0 + w);
        for (int j = lane; j < SS; j += 32) {
            float a = s_sc[w][j] * inv;
            s_sc[w][j] = a;
            out_att[r * SS + j] = a;
        }
    }
    __syncthreads();

    // ---- AV: thread owns d = {2*tid, 2*tid+1}; ctx[r0+i][d] = sum_j a*V ----
    float2 cacc[4];
    #pragma unroll
    for (int i = 0; i < 4; i++) cacc[i] = make_float2(0.f, 0.f);
    const float2* V2 = (const float2*)(V + (size_t)jb * DD);

    for (int j = 0; j < SS; j += 4) {
        float4 a0 = *(const float4*)&s_sc[0][j];
        float4 a1 = *(const float4*)&s_sc[1][j];
        float4 a2 = *(const float4*)&s_sc[2][j];
        float4 a3 = *(const float4*)&s_sc[3][j];
        #pragma unroll
        for (int jj = 0; jj < 4; jj++) {
            float2 vv = __ldg(&V2[(j + jj) * (DD/2) + tid]);
            float w0 = ((const float*)&a0)[jj];
            float w1 = ((const float*)&a1)[jj];
            float w2 = ((const float*)&a2)[jj];
            float w3 = ((const float*)&a3)[jj];
            cacc[0].x = fmaf(w0, vv.x, cacc[0].x); cacc[0].y = fmaf(w0, vv.y, cacc[0].y);
            cacc[1].x = fmaf(w1, vv.x, cacc[1].x); cacc[1].y = fmaf(w1, vv.y, cacc[1].y);
            cacc[2].x = fmaf(w2, vv.x, cacc[2].x); cacc[2].y = fmaf(w2, vv.y, cacc[2].y);
            cacc[3].x = fmaf(w3, vv.x, cacc[3].x); cacc[3].y = fmaf(w3, vv.y, cacc[3].y);
        }
    }
    #pragma unroll
    for (int i = 0; i < 4; i++)
        *(float2*)&out_ctx[(size_t)(r0 + i) * DD + 2 * tid] = cacc[i];
}

extern "C" void kernel_launch(void* const* d_in, const int* in_sizes, int n_in,
                              void* d_out, int out_size) {
    (void)in_sizes; (void)n_in; (void)out_size;
    const float* Q  = (const float*)d_in[0];
    // d_in[1] = key: unused by the reference computation
    const float* V  = (const float*)d_in[2];
    const float* Wm = (const float*)d_in[3];
    const float* vm = (const float*)d_in[4];
    float* out      = (float*)d_out;
    float* out_ctx  = out;              // context [B,S,D]
    float* out_att  = out + BS * DD;    // atten   [B,S,S]

    k1_proj<<<BS / TI, 256>>>(Q, Wm);
    k2_attn<<<BS / 4, 128>>>(V, vm, out_ctx, out_att);
}

// round 4
// speedup vs baseline: 1.9327x; 1.2471x over previous
#include <cuda_runtime.h>

#define BB 2
#define SS 512
#define DD 256
#define BS (BB*SS)
#define TI 8

// Scratch (allocation-free rule: __device__ globals).
__device__ float g_ET[BB*DD*SS];  // E transposed: [b][e][j] = exp(2*P[b][j][e])
__device__ float g_R [BS*DD];     // R row-major:  [r][e]    = exp(-2*P[r][e])

__device__ __forceinline__ float frcp_approx(float x){
    float r; asm("rcp.approx.f32 %0, %1;" : "=f"(r) : "f"(x)); return r;
}

// K1: P = Q @ Wm^T; then E_T = exp(2P) (transposed store), R = exp(-2P).
__global__ void __launch_bounds__(256) k1_proj(const float* __restrict__ Q,
                                               const float* __restrict__ W){
    __shared__ float sQT[DD][TI];
    __shared__ float sW[256][33];
    const int tid = threadIdx.x;
    const int r0  = blockIdx.x * TI;

    #pragma unroll
    for (int m = 0; m < TI; m++) sQT[tid][m] = Q[(r0 + m) * DD + tid];

    float acc[TI];
    #pragma unroll
    for (int m = 0; m < TI; m++) acc[m] = 0.f;

    for (int k0 = 0; k0 < DD; k0 += 32) {
        __syncthreads();
        #pragma unroll
        for (int i = 0; i < 8; i++) {
            int j4 = i * 256 + tid;
            int n  = j4 >> 3;
            int c4 = (j4 & 7) * 4;
            float4 w4 = *(const float4*)(W + n * DD + k0 + c4);
            sW[n][c4 + 0] = w4.x; sW[n][c4 + 1] = w4.y;
            sW[n][c4 + 2] = w4.z; sW[n][c4 + 3] = w4.w;
        }
        __syncthreads();
        #pragma unroll
        for (int c = 0; c < 32; c++) {
            float w = sW[tid][c];
            float4 q0 = *(const float4*)&sQT[k0 + c][0];
            float4 q1 = *(const float4*)&sQT[k0 + c][4];
            acc[0] = fmaf(w, q0.x, acc[0]); acc[1] = fmaf(w, q0.y, acc[1]);
            acc[2] = fmaf(w, q0.z, acc[2]); acc[3] = fmaf(w, q0.w, acc[3]);
            acc[4] = fmaf(w, q1.x, acc[4]); acc[5] = fmaf(w, q1.y, acc[5]);
            acc[6] = fmaf(w, q1.z, acc[6]); acc[7] = fmaf(w, q1.w, acc[7]);
        }
    }

    const float C2 = 2.885390081777927f; // 2*log2(e)
    const int b  = r0 / SS;
    const int jr = r0 % SS;
    #pragma unroll
    for (int m = 0; m < TI; m++) {
        float p = acc[m];
        g_ET[(size_t)b * DD * SS + (size_t)tid * SS + (jr + m)] = exp2f( C2 * p);
        g_R [(size_t)(r0 + m) * DD + tid]                       = exp2f(-C2 * p);
    }
}

// K2: block=256 (8 warps), i-tile=4, full j=512.
// Score phase: two 128-thread groups split the e-dimension (0-127 / 128-255),
// each thread owns one j-float4 x 4 i, with register double-buffered E prefetch.
// Partials combined in smem during softmax. AV: j-half split + smem combine.
__global__ void __launch_bounds__(256) k2_attn(const float* __restrict__ V,
                                               const float* __restrict__ vm,
                                               float* __restrict__ out_ctx,
                                               float* __restrict__ out_att){
    __shared__ float sR[4][264];
    __shared__ float sm2[256];
    __shared__ float s_sc0[4][516];   // group0 partials -> combined -> atten
    __shared__ float s_sc1[4][516];   // group1 partials
    __shared__ float s_av[4][256];    // AV partial combine
    __shared__ float s_red[8];

    const int tid  = threadIdx.x;
    const int lane = tid & 31;
    const int w    = tid >> 5;
    const int grp  = tid >> 7;        // e-group (0/1)
    const int gt   = tid & 127;       // thread-in-group = j-float4 index
    const int r0   = blockIdx.x * 4;
    const int b    = r0 >> 9;
    const int jb   = b << 9;

    // Stage: one e per thread.
    {
        float vme = vm[tid];
        sm2[tid] = -2.f * vme;
        #pragma unroll
        for (int i = 0; i < 4; i++) sR[i][tid] = g_R[(size_t)(r0 + i) * DD + tid];
        float svp = vme;
        #pragma unroll
        for (int off = 16; off; off >>= 1) svp += __shfl_xor_sync(0xffffffffu, svp, off);
        if (lane == 0) s_red[w] = svp;
    }
    __syncthreads();
    const float sv = s_red[0] + s_red[1] + s_red[2] + s_red[3] +
                     s_red[4] + s_red[5] + s_red[6] + s_red[7];

    // ---- Score phase: e in [grp*128, grp*128+128), 32 chunks of 4 e ----
    float acc[4][4];
    #pragma unroll
    for (int i = 0; i < 4; i++)
        #pragma unroll
        for (int c = 0; c < 4; c++) acc[i][c] = 0.f;

    {
        const float4* p = (const float4*)(g_ET + (size_t)b * DD * SS)
                          + (size_t)(grp * 128) * 128 + gt;
        int e = grp * 128;
        float4 n0 = p[0], n1 = p[128], n2 = p[256], n3 = p[384];
        p += 512;

        for (int chunk = 0; chunk < 32; chunk++) {
            float4 ev0 = n0, ev1 = n1, ev2 = n2, ev3 = n3;
            if (chunk < 31) { n0 = p[0]; n1 = p[128]; n2 = p[256]; n3 = p[384]; p += 512; }
            float4 m2 = *(const float4*)&sm2[e];
            #pragma unroll
            for (int i = 0; i < 4; i++) {
                float4 rv = *(const float4*)&sR[i][e];
                acc[i][0] = fmaf(m2.x, frcp_approx(fmaf(ev0.x, rv.x, 1.f)), acc[i][0]);
                acc[i][1] = fmaf(m2.x, frcp_approx(fmaf(ev0.y, rv.x, 1.f)), acc[i][1]);
                acc[i][2] = fmaf(m2.x, frcp_approx(fmaf(ev0.z, rv.x, 1.f)), acc[i][2]);
                acc[i][3] = fmaf(m2.x, frcp_approx(fmaf(ev0.w, rv.x, 1.f)), acc[i][3]);

                acc[i][0] = fmaf(m2.y, frcp_approx(fmaf(ev1.x, rv.y, 1.f)), acc[i][0]);
                acc[i][1] = fmaf(m2.y, frcp_approx(fmaf(ev1.y, rv.y, 1.f)), acc[i][1]);
                acc[i][2] = fmaf(m2.y, frcp_approx(fmaf(ev1.z, rv.y, 1.f)), acc[i][2]);
                acc[i][3] = fmaf(m2.y, frcp_approx(fmaf(ev1.w, rv.y, 1.f)), acc[i][3]);

                acc[i][0] = fmaf(m2.z, frcp_approx(fmaf(ev2.x, rv.z, 1.f)), acc[i][0]);
                acc[i][1] = fmaf(m2.z, frcp_approx(fmaf(ev2.y, rv.z, 1.f)), acc[i][1]);
                acc[i][2] = fmaf(m2.z, frcp_approx(fmaf(ev2.z, rv.z, 1.f)), acc[i][2]);
                acc[i][3] = fmaf(m2.z, frcp_approx(fmaf(ev2.w, rv.z, 1.f)), acc[i][3]);

                acc[i][0] = fmaf(m2.w, frcp_approx(fmaf(ev3.x, rv.w, 1.f)), acc[i][0]);
                acc[i][1] = fmaf(m2.w, frcp_approx(fmaf(ev3.y, rv.w, 1.f)), acc[i][1]);
                acc[i][2] = fmaf(m2.w, frcp_approx(fmaf(ev3.z, rv.w, 1.f)), acc[i][2]);
                acc[i][3] = fmaf(m2.w, frcp_approx(fmaf(ev3.w, rv.w, 1.f)), acc[i][3]);
            }
            e += 4;
        }
    }

    // Write group partials (STS.128, conflict-free)
    {
        const int j0 = gt * 4;
        float (*dst)[516] = grp ? s_sc1 : s_sc0;
        #pragma unroll
        for (int i = 0; i < 4; i++)
            *(float4*)&dst[i][j0] = make_float4(acc[i][0], acc[i][1], acc[i][2], acc[i][3]);
    }
    __syncthreads();

    // ---- Softmax: warp w<4 owns row r0+w; combine partials in max pass ----
    if (w < 4) {
        float mx = -1e30f;
        #pragma unroll
        for (int jf = lane; jf < 128; jf += 32) {
            float4 a = *(const float4*)&s_sc0[w][jf * 4];
            float4 c = *(const float4*)&s_sc1[w][jf * 4];
            a.x += c.x + sv; a.y += c.y + sv; a.z += c.z + sv; a.w += c.w + sv;
            *(float4*)&s_sc0[w][jf * 4] = a;
            mx = fmaxf(mx, fmaxf(fmaxf(a.x, a.y), fmaxf(a.z, a.w)));
        }
        #pragma unroll
        for (int off = 16; off; off >>= 1)
            mx = fmaxf(mx, __shfl_xor_sync(0xffffffffu, mx, off));
        float sum = 0.f;
        #pragma unroll
        for (int jf = lane; jf < 128; jf += 32) {
            float4 a = *(const float4*)&s_sc0[w][jf * 4];
            a.x = __expf(a.x - mx); a.y = __expf(a.y - mx);
            a.z = __expf(a.z - mx); a.w = __expf(a.w - mx);
            *(float4*)&s_sc0[w][jf * 4] = a;
            sum += a.x + a.y + a.z + a.w;
        }
        #pragma unroll
        for (int off = 16; off; off >>= 1)
            sum += __shfl_xor_sync(0xffffffffu, sum, off);
        float inv = 1.f / sum;
        const size_t r = (size_t)(r0 + w);
        #pragma unroll
        for (int jf = lane; jf < 128; jf += 32) {
            float4 a = *(const float4*)&s_sc0[w][jf * 4];
            a.x *= inv; a.y *= inv; a.z *= inv; a.w *= inv;
            *(float4*)&s_sc0[w][jf * 4] = a;
            *(float4*)&out_att[r * SS + jf * 4] = a;
        }
    }
    __syncthreads();

    // ---- AV: j-half split. Thread: d2 = gt (float2 col), j in [grp*256, +256) ----
    float2 cacc[4];
    #pragma unroll
    for (int i = 0; i < 4; i++) cacc[i] = make_float2(0.f, 0.f);
    {
        const float2* V2 = (const float2*)(V + (size_t)jb * DD);
        const int jA = grp * 256;
        for (int j = jA; j < jA + 256; j += 4) {
            float4 a0 = *(const float4*)&s_sc0[0][j];
            float4 a1 = *(const float4*)&s_sc0[1][j];
            float4 a2 = *(const float4*)&s_sc0[2][j];
            float4 a3 = *(const float4*)&s_sc0[3][j];
            #pragma unroll
            for (int jj = 0; jj < 4; jj++) {
                float2 vv = __ldg(&V2[(size_t)(j + jj) * (DD/2) + gt]);
                float w0 = ((const float*)&a0)[jj];
                float w1 = ((const float*)&a1)[jj];
                float w2 = ((const float*)&a2)[jj];
                float w3 = ((const float*)&a3)[jj];
                cacc[0].x = fmaf(w0, vv.x, cacc[0].x); cacc[0].y = fmaf(w0, vv.y, cacc[0].y);
                cacc[1].x = fmaf(w1, vv.x, cacc[1].x); cacc[1].y = fmaf(w1, vv.y, cacc[1].y);
                cacc[2].x = fmaf(w2, vv.x, cacc[2].x); cacc[2].y = fmaf(w2, vv.y, cacc[2].y);
                cacc[3].x = fmaf(w3, vv.x, cacc[3].x); cacc[3].y = fmaf(w3, vv.y, cacc[3].y);
            }
        }
    }
    // Combine halves: group0 deposits, group1 adds and stores.
    if (grp == 0) {
        #pragma unroll
        for (int i = 0; i < 4; i++) *(float2*)&s_av[i][2 * gt] = cacc[i];
    }
    __syncthreads();
    if (grp == 1) {
        #pragma unroll
        for (int i = 0; i < 4; i++) {
            float2 p0 = *(const float2*)&s_av[i][2 * gt];
            float2 r  = make_float2(cacc[i].x + p0.x, cacc[i].y + p0.y);
            *(float2*)&out_ctx[(size_t)(r0 + i) * DD + 2 * gt] = r;
        }
    }
}

extern "C" void kernel_launch(void* const* d_in, const int* in_sizes, int n_in,
                              void* d_out, int out_size) {
    (void)in_sizes; (void)n_in; (void)out_size;
    const float* Q  = (const float*)d_in[0];
    const float* V  = (const float*)d_in[2];
    const float* Wm = (const float*)d_in[3];
    const float* vm = (const float*)d_in[4];
    float* out      = (float*)d_out;
    float* out_ctx  = out;              // context [B,S,D]
    float* out_att  = out + BS * DD;    // atten   [B,S,S]

    k1_proj<<<BS / TI, 256>>>(Q, Wm);
    k2_attn<<<BS / 4, 256>>>(V, vm, out_ctx, out_att);
}

// round 5
// speedup vs baseline: 1.9756x; 1.0222x over previous
#include <cuda_runtime.h>

#define BB 2
#define SS 512
#define DD 256
#define BS (BB*SS)

// Scratch (allocation-free rule: __device__ globals).
__device__ float g_ET[BB*DD*SS];  // E transposed: [b][e][j] = exp(2*P[b][j][e])
__device__ float g_R [BS*DD];     // R row-major:  [r][e]    = exp(-2*P[r][e])

__device__ __forceinline__ float frcp_approx(float x){
    float r; asm("rcp.approx.f32 %0, %1;" : "=f"(r) : "f"(x)); return r;
}

// K1: P = Q @ Wm^T; then E_T = exp(2P) (transposed store), R = exp(-2P).
// i-tile = 4 -> grid 256 (cover all SMs). Thread e owns output column e.
__global__ void __launch_bounds__(256) k1_proj(const float* __restrict__ Q,
                                               const float* __restrict__ W){
    __shared__ float sQT[DD][4];
    __shared__ float sW[256][33];
    const int tid = threadIdx.x;
    const int r0  = blockIdx.x * 4;

    #pragma unroll
    for (int m = 0; m < 4; m++) sQT[tid][m] = Q[(r0 + m) * DD + tid];

    float acc[4] = {0.f, 0.f, 0.f, 0.f};

    for (int k0 = 0; k0 < DD; k0 += 32) {
        __syncthreads();
        #pragma unroll
        for (int i = 0; i < 8; i++) {
            int j4 = i * 256 + tid;
            int n  = j4 >> 3;
            int c4 = (j4 & 7) * 4;
            float4 w4 = *(const float4*)(W + n * DD + k0 + c4);
            sW[n][c4 + 0] = w4.x; sW[n][c4 + 1] = w4.y;
            sW[n][c4 + 2] = w4.z; sW[n][c4 + 3] = w4.w;
        }
        __syncthreads();
        #pragma unroll
        for (int c = 0; c < 32; c++) {
            float w = sW[tid][c];
            float4 q0 = *(const float4*)&sQT[k0 + c][0];
            acc[0] = fmaf(w, q0.x, acc[0]); acc[1] = fmaf(w, q0.y, acc[1]);
            acc[2] = fmaf(w, q0.z, acc[2]); acc[3] = fmaf(w, q0.w, acc[3]);
        }
    }

    const float C2 = 2.885390081777927f; // 2*log2(e)
    const int b  = r0 / SS;
    const int jr = r0 % SS;
    #pragma unroll
    for (int m = 0; m < 4; m++) {
        float p = acc[m];
        g_ET[(size_t)b * DD * SS + (size_t)tid * SS + (jr + m)] = exp2f( C2 * p);
        g_R [(size_t)(r0 + m) * DD + tid]                       = exp2f(-C2 * p);
    }
}

// K2: block=256 (8 warps), i-tile=2, full j=512, grid=512.
// Score phase: two 128-thread groups split e (0-127 / 128-255); each thread owns
// one j-float4 x 2 i with register double-buffered E prefetch. Partials combined
// in smem at softmax. AV: j-half split + smem combine.
__global__ void __launch_bounds__(256) k2_attn(const float* __restrict__ V,
                                               const float* __restrict__ vm,
                                               float* __restrict__ out_ctx,
                                               float* __restrict__ out_att){
    __shared__ float sR[2][264];
    __shared__ float sm2[256];
    __shared__ float s_sc0[2][516];   // group0 partials -> combined -> atten
    __shared__ float s_sc1[2][516];   // group1 partials
    __shared__ float s_av[2][256];    // AV partial combine
    __shared__ float s_red[8];

    const int tid  = threadIdx.x;
    const int lane = tid & 31;
    const int w    = tid >> 5;
    const int grp  = tid >> 7;        // e-group (0/1)
    const int gt   = tid & 127;       // thread-in-group = j-float4 index
    const int r0   = blockIdx.x * 2;
    const int b    = r0 >> 9;         // r0 / SS
    const int jb   = b << 9;

    // Stage: one e per thread.
    {
        float vme = vm[tid];
        sm2[tid] = -2.f * vme;
        #pragma unroll
        for (int i = 0; i < 2; i++) sR[i][tid] = g_R[(size_t)(r0 + i) * DD + tid];
        float svp = vme;
        #pragma unroll
        for (int off = 16; off; off >>= 1) svp += __shfl_xor_sync(0xffffffffu, svp, off);
        if (lane == 0) s_red[w] = svp;
    }
    __syncthreads();
    const float sv = s_red[0] + s_red[1] + s_red[2] + s_red[3] +
                     s_red[4] + s_red[5] + s_red[6] + s_red[7];

    // ---- Score phase: e in [grp*128, grp*128+128), 32 chunks of 4 e ----
    float acc[2][4];
    #pragma unroll
    for (int i = 0; i < 2; i++)
        #pragma unroll
        for (int c = 0; c < 4; c++) acc[i][c] = 0.f;

    {
        const float4* p = (const float4*)(g_ET + (size_t)b * DD * SS)
                          + (size_t)(grp * 128) * 128 + gt;
        int e = grp * 128;
        float4 n0 = p[0], n1 = p[128], n2 = p[256], n3 = p[384];
        p += 512;

        for (int chunk = 0; chunk < 32; chunk++) {
            float4 ev0 = n0, ev1 = n1, ev2 = n2, ev3 = n3;
            if (chunk < 31) { n0 = p[0]; n1 = p[128]; n2 = p[256]; n3 = p[384]; p += 512; }
            float4 m2 = *(const float4*)&sm2[e];
            #pragma unroll
            for (int i = 0; i < 2; i++) {
                float4 rv = *(const float4*)&sR[i][e];
                acc[i][0] = fmaf(m2.x, frcp_approx(fmaf(ev0.x, rv.x, 1.f)), acc[i][0]);
                acc[i][1] = fmaf(m2.x, frcp_approx(fmaf(ev0.y, rv.x, 1.f)), acc[i][1]);
                acc[i][2] = fmaf(m2.x, frcp_approx(fmaf(ev0.z, rv.x, 1.f)), acc[i][2]);
                acc[i][3] = fmaf(m2.x, frcp_approx(fmaf(ev0.w, rv.x, 1.f)), acc[i][3]);

                acc[i][0] = fmaf(m2.y, frcp_approx(fmaf(ev1.x, rv.y, 1.f)), acc[i][0]);
                acc[i][1] = fmaf(m2.y, frcp_approx(fmaf(ev1.y, rv.y, 1.f)), acc[i][1]);
                acc[i][2] = fmaf(m2.y, frcp_approx(fmaf(ev1.z, rv.y, 1.f)), acc[i][2]);
                acc[i][3] = fmaf(m2.y, frcp_approx(fmaf(ev1.w, rv.y, 1.f)), acc[i][3]);

                acc[i][0] = fmaf(m2.z, frcp_approx(fmaf(ev2.x, rv.z, 1.f)), acc[i][0]);
                acc[i][1] = fmaf(m2.z, frcp_approx(fmaf(ev2.y, rv.z, 1.f)), acc[i][1]);
                acc[i][2] = fmaf(m2.z, frcp_approx(fmaf(ev2.z, rv.z, 1.f)), acc[i][2]);
                acc[i][3] = fmaf(m2.z, frcp_approx(fmaf(ev2.w, rv.z, 1.f)), acc[i][3]);

                acc[i][0] = fmaf(m2.w, frcp_approx(fmaf(ev3.x, rv.w, 1.f)), acc[i][0]);
                acc[i][1] = fmaf(m2.w, frcp_approx(fmaf(ev3.y, rv.w, 1.f)), acc[i][1]);
                acc[i][2] = fmaf(m2.w, frcp_approx(fmaf(ev3.z, rv.w, 1.f)), acc[i][2]);
                acc[i][3] = fmaf(m2.w, frcp_approx(fmaf(ev3.w, rv.w, 1.f)), acc[i][3]);
            }
            e += 4;
        }
    }

    // Write group partials (STS.128, conflict-free)
    {
        const int j0 = gt * 4;
        float (*dst)[516] = grp ? s_sc1 : s_sc0;
        #pragma unroll
        for (int i = 0; i < 2; i++)
            *(float4*)&dst[i][j0] = make_float4(acc[i][0], acc[i][1], acc[i][2], acc[i][3]);
    }
    __syncthreads();

    // ---- Softmax: warp w<2 owns row r0+w; combine partials in max pass ----
    if (w < 2) {
        float mx = -1e30f;
        #pragma unroll
        for (int jf = lane; jf < 128; jf += 32) {
            float4 a = *(const float4*)&s_sc0[w][jf * 4];
            float4 c = *(const float4*)&s_sc1[w][jf * 4];
            a.x += c.x + sv; a.y += c.y + sv; a.z += c.z + sv; a.w += c.w + sv;
            *(float4*)&s_sc0[w][jf * 4] = a;
            mx = fmaxf(mx, fmaxf(fmaxf(a.x, a.y), fmaxf(a.z, a.w)));
        }
        #pragma unroll
        for (int off = 16; off; off >>= 1)
            mx = fmaxf(mx, __shfl_xor_sync(0xffffffffu, mx, off));
        float sum = 0.f;
        #pragma unroll
        for (int jf = lane; jf < 128; jf += 32) {
            float4 a = *(const float4*)&s_sc0[w][jf * 4];
            a.x = __expf(a.x - mx); a.y = __expf(a.y - mx);
            a.z = __expf(a.z - mx); a.w = __expf(a.w - mx);
            *(float4*)&s_sc0[w][jf * 4] = a;
            sum += a.x + a.y + a.z + a.w;
        }
        #pragma unroll
        for (int off = 16; off; off >>= 1)
            sum += __shfl_xor_sync(0xffffffffu, sum, off);
        float inv = 1.f / sum;
        const size_t r = (size_t)(r0 + w);
        #pragma unroll
        for (int jf = lane; jf < 128; jf += 32) {
            float4 a = *(const float4*)&s_sc0[w][jf * 4];
            a.x *= inv; a.y *= inv; a.z *= inv; a.w *= inv;
            *(float4*)&s_sc0[w][jf * 4] = a;
            *(float4*)&out_att[r * SS + jf * 4] = a;
        }
    }
    __syncthreads();

    // ---- AV: j-half split. Thread: d2 = gt (float2 col), j in [grp*256, +256) ----
    float2 cacc[2];
    #pragma unroll
    for (int i = 0; i < 2; i++) cacc[i] = make_float2(0.f, 0.f);
    {
        const float2* V2 = (const float2*)(V + (size_t)jb * DD);
        const int jA = grp * 256;
        for (int j = jA; j < jA + 256; j += 4) {
            float4 a0 = *(const float4*)&s_sc0[0][j];
            float4 a1 = *(const float4*)&s_sc0[1][j];
            #pragma unroll
            for (int jj = 0; jj < 4; jj++) {
                float2 vv = __ldg(&V2[(size_t)(j + jj) * (DD/2) + gt]);
                float w0 = ((const float*)&a0)[jj];
                float w1 = ((const float*)&a1)[jj];
                cacc[0].x = fmaf(w0, vv.x, cacc[0].x); cacc[0].y = fmaf(w0, vv.y, cacc[0].y);
                cacc[1].x = fmaf(w1, vv.x, cacc[1].x); cacc[1].y = fmaf(w1, vv.y, cacc[1].y);
            }
        }
    }
    // Combine halves: group0 deposits, group1 adds and stores.
    if (grp == 0) {
        #pragma unroll
        for (int i = 0; i < 2; i++) *(float2*)&s_av[i][2 * gt] = cacc[i];
    }
    __syncthreads();
    if (grp == 1) {
        #pragma unroll
        for (int i = 0; i < 2; i++) {
            float2 p0 = *(const float2*)&s_av[i][2 * gt];
            float2 r  = make_float2(cacc[i].x + p0.x, cacc[i].y + p0.y);
            *(float2*)&out_ctx[(size_t)(r0 + i) * DD + 2 * gt] = r;
        }
    }
}

extern "C" void kernel_launch(void* const* d_in, const int* in_sizes, int n_in,
                              void* d_out, int out_size) {
    (void)in_sizes; (void)n_in; (void)out_size;
    const float* Q  = (const float*)d_in[0];
    const float* V  = (const float*)d_in[2];
    const float* Wm = (const float*)d_in[3];
    const float* vm = (const float*)d_in[4];
    float* out      = (float*)d_out;
    float* out_ctx  = out;              // context [B,S,D]
    float* out_att  = out + BS * DD;    // atten   [B,S,S]

    k1_proj<<<BS / 4, 256>>>(Q, Wm);
    k2_attn<<<BS / 2, 256>>>(V, vm, out_ctx, out_att);
}

// round 7
// speedup vs baseline: 2.1310x; 1.0787x over previous
#include <cuda_runtime.h>

#define BB 2
#define SS 512
#define DD 256
#define BS (BB*SS)
#define NT 16            // 512/32 j-tiles per dim
#define NP 136           // NT*(NT+1)/2 triangular tile pairs

// Scratch (allocation-free rule: __device__ globals).
__device__ float g_ET[BB*DD*SS];  // E transposed: [b][e][j] = exp(2*P[b][j][e])
__device__ float g_R [BS*DD];     // R row-major:  [r][e]    = exp(-2*P[r][e])
__device__ float g_S [BS*SS];     // raw scores   [r][j]

__device__ __forceinline__ float frcp_approx(float x){
    float r; asm("rcp.approx.f32 %0, %1;" : "=f"(r) : "f"(x)); return r;
}

// K1: P = Q @ Wm^T; then E_T = exp(2P) (transposed store), R = exp(-2P).
__global__ void __launch_bounds__(256) k1_proj(const float* __restrict__ Q,
                                               const float* __restrict__ W){
    __shared__ float sQT[DD][4];
    __shared__ float sW[256][33];
    const int tid = threadIdx.x;
    const int r0  = blockIdx.x * 4;

    #pragma unroll
    for (int m = 0; m < 4; m++) sQT[tid][m] = Q[(r0 + m) * DD + tid];

    float acc[4] = {0.f, 0.f, 0.f, 0.f};

    for (int k0 = 0; k0 < DD; k0 += 32) {
        __syncthreads();
        #pragma unroll
        for (int i = 0; i < 8; i++) {
            int j4 = i * 256 + tid;
            int n  = j4 >> 3;
            int c4 = (j4 & 7) * 4;
            float4 w4 = *(const float4*)(W + n * DD + k0 + c4);
            sW[n][c4 + 0] = w4.x; sW[n][c4 + 1] = w4.y;
            sW[n][c4 + 2] = w4.z; sW[n][c4 + 3] = w4.w;
        }
        __syncthreads();
        #pragma unroll
        for (int c = 0; c < 32; c++) {
            float w = sW[tid][c];
            float4 q0 = *(const float4*)&sQT[k0 + c][0];
            acc[0] = fmaf(w, q0.x, acc[0]); acc[1] = fmaf(w, q0.y, acc[1]);
            acc[2] = fmaf(w, q0.z, acc[2]); acc[3] = fmaf(w, q0.w, acc[3]);
        }
    }

    const float C2 = 2.885390081777927f; // 2*log2(e)
    const int b  = r0 / SS;
    const int jr = r0 % SS;
    #pragma unroll
    for (int m = 0; m < 4; m++) {
        float p = acc[m];
        g_ET[(size_t)b * DD * SS + (size_t)tid * SS + (jr + m)] = exp2f( C2 * p);
        g_R [(size_t)(r0 + m) * DD + tid]                       = exp2f(-C2 * p);
    }
}

// K2s: scores for one 32x32 tile pair (ti<=tj) via antisymmetry.
// Block 256 = 2 e-groups x 128; thread = (i, 2 j-float4). Writes direct tile
// and (if off-diagonal) negated transpose.
__global__ void __launch_bounds__(256) k2_scores(const float* __restrict__ vm){
    __shared__ __align__(16) float sR[32][260];   // R tile; reused after e-loop
    __shared__ float sm2[256];
    __shared__ float s_red[8];

    const int tid  = threadIdx.x;
    const int lane = tid & 31;
    const int w    = tid >> 5;
    const int b    = blockIdx.x / NP;
    int p = blockIdx.x - b * NP;
    int ti = 0;
    while (p >= NT - ti) { p -= NT - ti; ti++; }
    const int tj = ti + p;
    const int I = ti * 32, J = tj * 32;

    // vm staging + sum(vm)
    {
        float vme = vm[tid];
        sm2[tid] = -2.f * vme;
        float svp = vme;
        #pragma unroll
        for (int off = 16; off; off >>= 1) svp += __shfl_xor_sync(0xffffffffu, svp, off);
        if (lane == 0) s_red[w] = svp;
    }
    // R tile staging (2048 float4, coalesced)
    {
        const float4* R4 = (const float4*)(g_R + (size_t)(b * SS + I) * DD);
        #pragma unroll
        for (int k = 0; k < 8; k++) {
            int lin = k * 256 + tid;
            int row = lin >> 6;
            int c4  = lin & 63;
            float4 v = R4[row * 64 + c4];
            *(float4*)&sR[row][c4 * 4] = v;
        }
    }
    __syncthreads();
    const float sv = s_red[0] + s_red[1] + s_red[2] + s_red[3] +
                     s_red[4] + s_red[5] + s_red[6] + s_red[7];

    const int grp  = tid >> 7;
    const int t    = tid & 127;
    const int i    = t >> 2;
    const int col0 = tj * 8 + (t & 3) * 2;

    float4 acc0 = {0,0,0,0}, acc1 = {0,0,0,0};
    {
        const float4* EB = (const float4*)(g_ET + (size_t)b * DD * SS);
        const int e0 = grp * 128;
        const float4* pe = EB + (size_t)e0 * (SS/4) + col0;
        float4 n0 = pe[0],   n1 = pe[1];
        float4 n2 = pe[128], n3 = pe[129];
        float4 n4 = pe[256], n5 = pe[257];
        float4 n6 = pe[384], n7 = pe[385];
        pe += 512;

        for (int chunk = 0; chunk < 32; chunk++) {
            float4 c0=n0,c1=n1,c2=n2,c3=n3,c4=n4,c5=n5,c6=n6,c7=n7;
            if (chunk < 31) {
                n0=pe[0];   n1=pe[1];
                n2=pe[128]; n3=pe[129];
                n4=pe[256]; n5=pe[257];
                n6=pe[384]; n7=pe[385];
                pe += 512;
            }
            const int e = e0 + chunk * 4;
            float4 r4 = *(const float4*)&sR[i][e];
            float4 m4 = *(const float4*)&sm2[e];

            acc0.x = fmaf(m4.x, frcp_approx(fmaf(c0.x, r4.x, 1.f)), acc0.x);
            acc0.y = fmaf(m4.x, frcp_approx(fmaf(c0.y, r4.x, 1.f)), acc0.y);
            acc0.z = fmaf(m4.x, frcp_approx(fmaf(c0.z, r4.x, 1.f)), acc0.z);
            acc0.w = fmaf(m4.x, frcp_approx(fmaf(c0.w, r4.x, 1.f)), acc0.w);
            acc1.x = fmaf(m4.x, frcp_approx(fmaf(c1.x, r4.x, 1.f)), acc1.x);
            acc1.y = fmaf(m4.x, frcp_approx(fmaf(c1.y, r4.x, 1.f)), acc1.y);
            acc1.z = fmaf(m4.x, frcp_approx(fmaf(c1.z, r4.x, 1.f)), acc1.z);
            acc1.w = fmaf(m4.x, frcp_approx(fmaf(c1.w, r4.x, 1.f)), acc1.w);

            acc0.x = fmaf(m4.y, frcp_approx(fmaf(c2.x, r4.y, 1.f)), acc0.x);
            acc0.y = fmaf(m4.y, frcp_approx(fmaf(c2.y, r4.y, 1.f)), acc0.y);
            acc0.z = fmaf(m4.y, frcp_approx(fmaf(c2.z, r4.y, 1.f)), acc0.z);
            acc0.w = fmaf(m4.y, frcp_approx(fmaf(c2.w, r4.y, 1.f)), acc0.w);
            acc1.x = fmaf(m4.y, frcp_approx(fmaf(c3.x, r4.y, 1.f)), acc1.x);
            acc1.y = fmaf(m4.y, frcp_approx(fmaf(c3.y, r4.y, 1.f)), acc1.y);
            acc1.z = fmaf(m4.y, frcp_approx(fmaf(c3.z, r4.y, 1.f)), acc1.z);
            acc1.w = fmaf(m4.y, frcp_approx(fmaf(c3.w, r4.y, 1.f)), acc1.w);

            acc0.x = fmaf(m4.z, frcp_approx(fmaf(c4.x, r4.z, 1.f)), acc0.x);
            acc0.y = fmaf(m4.z, frcp_approx(fmaf(c4.y, r4.z, 1.f)), acc0.y);
            acc0.z = fmaf(m4.z, frcp_approx(fmaf(c4.z, r4.z, 1.f)), acc0.z);
            acc0.w = fmaf(m4.z, frcp_approx(fmaf(c4.w, r4.z, 1.f)), acc0.w);
            acc1.x = fmaf(m4.z, frcp_approx(fmaf(c5.x, r4.z, 1.f)), acc1.x);
            acc1.y = fmaf(m4.z, frcp_approx(fmaf(c5.y, r4.z, 1.f)), acc1.y);
            acc1.z = fmaf(m4.z, frcp_approx(fmaf(c5.z, r4.z, 1.f)), acc1.z);
            acc1.w = fmaf(m4.z, frcp_approx(fmaf(c5.w, r4.z, 1.f)), acc1.w);

            acc0.x = fmaf(m4.w, frcp_approx(fmaf(c6.x, r4.w, 1.f)), acc0.x);
            acc0.y = fmaf(m4.w, frcp_approx(fmaf(c6.y, r4.w, 1.f)), acc0.y);
            acc0.z = fmaf(m4.w, frcp_approx(fmaf(c6.z, r4.w, 1.f)), acc0.z);
            acc0.w = fmaf(m4.w, frcp_approx(fmaf(c6.w, r4.w, 1.f)), acc0.w);
            acc1.x = fmaf(m4.w, frcp_approx(fmaf(c7.x, r4.w, 1.f)), acc1.x);
            acc1.y = fmaf(m4.w, frcp_approx(fmaf(c7.y, r4.w, 1.f)), acc1.y);
            acc1.z = fmaf(m4.w, frcp_approx(fmaf(c7.z, r4.w, 1.f)), acc1.z);
            acc1.w = fmaf(m4.w, frcp_approx(fmaf(c7.w, r4.w, 1.f)), acc1.w);
        }
    }

    // Reuse sR storage: sp0[1024] | sp1[1024] | st[32][36]
    float* sp0 = &sR[0][0];
    float* sp1 = sp0 + 1024;
    float (*st)[36] = (float(*)[36])(sp1 + 1024);
    __syncthreads();                       // done reading sR
    {
        float* sp = grp ? sp1 : sp0;
        *(float4*)&sp[i * 32 + (t & 3) * 8]     = acc0;
        *(float4*)&sp[i * 32 + (t & 3) * 8 + 4] = acc1;
    }
    __syncthreads();
    {
        const int ii = tid >> 3, j0 = (tid & 7) * 4;
        float4 a  = *(const float4*)&sp0[ii * 32 + j0];
        float4 bb = *(const float4*)&sp1[ii * 32 + j0];
        float4 s  = make_float4(a.x + bb.x + sv, a.y + bb.y + sv,
                                a.z + bb.z + sv, a.w + bb.w + sv);
        *(float4*)&st[ii][j0] = s;
        *(float4*)&g_S[(size_t)(b * SS + I + ii) * SS + J + j0] = s;
    }
    if (ti != tj) {
        __syncthreads();
        const int j = tid >> 3, i0 = (tid & 7) * 4;
        float4 mv = make_float4(-st[i0 + 0][j], -st[i0 + 1][j],
                                -st[i0 + 2][j], -st[i0 + 3][j]);
        *(float4*)&g_S[(size_t)(b * SS + J + j) * SS + I + i0] = mv;
    }
}

// K3: softmax (no-max: |score| <= sum|vm|, overflow-safe) + tiled AV.
// grid = 32 row-tiles x 8 d-tiles. dt==0 blocks also write atten.
__global__ void __launch_bounds__(256) k3_av(const float* __restrict__ V,
                                             float* __restrict__ out_ctx,
                                             float* __restrict__ out_att){
    __shared__ __align__(16) float sA[32][68];
    __shared__ __align__(16) float sV[64][36];
    __shared__ float sRed[32][8];
    __shared__ float sInv[32];

    const int tid = threadIdx.x;
    const int rt  = blockIdx.x >> 3;
    const int dt  = blockIdx.x & 7;
    const int r0  = rt * 32;
    const int b   = r0 >> 9;
    const int jb  = b << 9;
    const int d0  = dt * 32;
    const int i   = tid >> 3;
    const int js  = tid & 7;
    const int dd  = tid & 7;

    // pass 1: sum of exp over the row (each thread a j-comb of 64 elems)
    {
        const float4* S4 = (const float4*)(g_S + (size_t)(r0 + i) * SS);
        float s = 0.f;
        #pragma unroll
        for (int k = 0; k < 16; k++) {
            float4 v = S4[js + k * 8];
            s += __expf(v.x) + __expf(v.y) + __expf(v.z) + __expf(v.w);
        }
        sRed[i][js] = s;
    }
    __syncthreads();
    if (tid < 32) {
        float S = 0.f;
        #pragma unroll
        for (int q = 0; q < 8; q++) S += sRed[tid][q];
        sInv[tid] = 1.f / S;
    }
    __syncthreads();

    const float inv = sInv[i];
    float4 acc = {0,0,0,0};

    for (int jc = 0; jc < 8; jc++) {
        // stage normalized atten chunk (row i, 64 j)
        {
            const float4* S4 = (const float4*)(g_S + (size_t)(r0 + i) * SS + jc * 64 + js * 8);
            float4 v0 = S4[0], v1 = S4[1];
            v0.x = __expf(v0.x) * inv; v0.y = __expf(v0.y) * inv;
            v0.z = __expf(v0.z) * inv; v0.w = __expf(v0.w) * inv;
            v1.x = __expf(v1.x) * inv; v1.y = __expf(v1.y) * inv;
            v1.z = __expf(v1.z) * inv; v1.w = __expf(v1.w) * inv;
            *(float4*)&sA[i][js * 8]     = v0;
            *(float4*)&sA[i][js * 8 + 4] = v1;
            if (dt == 0) {
                float4* O = (float4*)(out_att + (size_t)(r0 + i) * SS + jc * 64 + js * 8);
                O[0] = v0; O[1] = v1;
            }
        }
        // stage V chunk: 64 j-rows x 32 d-cols (8 floats per thread: FIXED)
        {
            const int jv = tid >> 2, c8 = (tid & 3) * 8;
            const float* Vp = V + (size_t)(jb + jc * 64 + jv) * DD + d0 + c8;
            float4 va = *(const float4*)(Vp);
            float4 vb = *(const float4*)(Vp + 4);
            *(float4*)&sV[jv][c8]     = va;
            *(float4*)&sV[jv][c8 + 4] = vb;
        }
        __syncthreads();
        #pragma unroll 8
        for (int j = 0; j < 64; j++) {
            float a   = sA[i][j];
            float4 v4 = *(const float4*)&sV[j][dd * 4];
            acc.x = fmaf(a, v4.x, acc.x);
            acc.y = fmaf(a, v4.y, acc.y);
            acc.z = fmaf(a, v4.z, acc.z);
            acc.w = fmaf(a, v4.w, acc.w);
        }
        __syncthreads();
    }
    *(float4*)&out_ctx[(size_t)(r0 + i) * DD + d0 + dd * 4] = acc;
}

extern "C" void kernel_launch(void* const* d_in, const int* in_sizes, int n_in,
                              void* d_out, int out_size) {
    (void)in_sizes; (void)n_in; (void)out_size;
    const float* Q  = (const float*)d_in[0];
    const float* V  = (const float*)d_in[2];
    const float* Wm = (const float*)d_in[3];
    const float* vm = (const float*)d_in[4];
    float* out      = (float*)d_out;
    float* out_ctx  = out;              // context [B,S,D]
    float* out_att  = out + BS * DD;    // atten   [B,S,S]

    k1_proj  <<<BS / 4, 256>>>(Q, Wm);
    k2_scores<<<BB * NP, 256>>>(vm);
    k3_av    <<<(BS / 32) * 8, 256>>>(V, out_ctx, out_att);
}